// round 15
// baseline (speedup 1.0000x reference)
#include <cuda_runtime.h>
#include <cuda_fp16.h>
#include <cstdint>

// Fused NeRF: hybrid sincos — MUFU for bands 1/10.08 (small args), packed-FMA
// Cody-Waite for bands 101.6/1024 (pipe balancing: SFU was ~48% busy) +
// layer1 mma.sync.m16n8k16 fp16 (b1 in C-init) + layer2 via MMA (W2 hi+mid,
// b2 in D-init). Base-sm_100. R14: SFU/FMA rebalance + 6 blocks/SM.

typedef unsigned long long u64;

#define TPB 128
#define ITER 8
#define NIN 27
#define HID 32

__device__ __forceinline__ u64 pack2(float a, float b) {
    u64 r; asm("mov.b64 %0, {%1,%2};" : "=l"(r) : "f"(a), "f"(b)); return r;
}
__device__ __forceinline__ void unpack2(u64 v, float& a, float& b) {
    asm("mov.b64 {%0,%1}, %2;" : "=f"(a), "=f"(b) : "l"(v));
}
__device__ __forceinline__ u64 pack2u(uint32_t a, uint32_t b) {
    u64 r; asm("mov.b64 %0, {%1,%2};" : "=l"(r) : "r"(a), "r"(b)); return r;
}
__device__ __forceinline__ u64 fma2(u64 a, u64 b, u64 c) {
    u64 d; asm("fma.rn.f32x2 %0, %1, %2, %3;" : "=l"(d) : "l"(a), "l"(b), "l"(c)); return d;
}
__device__ __forceinline__ u64 mul2(u64 a, u64 b) {
    u64 d; asm("mul.rn.f32x2 %0, %1, %2;" : "=l"(d) : "l"(a), "l"(b)); return d;
}
__device__ __forceinline__ u64 sub2(u64 a, u64 b) {
    u64 d; asm("sub.rn.f32x2 %0, %1, %2;" : "=l"(d) : "l"(a), "l"(b)); return d;
}
#define K2(v) pack2((v), (v))
// d = { f16(a) in low half, f16(b) in high half }
#define CVT_F16X2(result, a, b) \
    asm("cvt.rn.f16x2.f32 %0, %1, %2;" : "=r"(result) : "f"(b), "f"(a))

__device__ __forceinline__ uint32_t smem_u32(const void* p) {
    uint32_t a; asm("{ .reg .u64 t; cvta.to.shared.u64 t, %1; cvt.u32.u64 %0, t; }" : "=r"(a) : "l"(p));
    return a;
}
__device__ __forceinline__ void ldmatrix_x4(uint32_t& r0, uint32_t& r1, uint32_t& r2, uint32_t& r3, uint32_t addr) {
    asm volatile("ldmatrix.sync.aligned.m8n8.x4.shared.b16 {%0,%1,%2,%3}, [%4];"
                 : "=r"(r0), "=r"(r1), "=r"(r2), "=r"(r3) : "r"(addr));
}
__device__ __forceinline__ void ldmatrix_x2(uint32_t& r0, uint32_t& r1, uint32_t addr) {
    asm volatile("ldmatrix.sync.aligned.m8n8.x2.shared.b16 {%0,%1}, [%2];"
                 : "=r"(r0), "=r"(r1) : "r"(addr));
}
__device__ __forceinline__ void mma16816(float* c, const uint32_t* a, uint32_t b0, uint32_t b1) {
    asm volatile("mma.sync.aligned.m16n8k16.row.col.f32.f16.f16.f32 "
                 "{%0,%1,%2,%3},{%4,%5,%6,%7},{%8,%9},{%0,%1,%2,%3};"
                 : "+f"(c[0]), "+f"(c[1]), "+f"(c[2]), "+f"(c[3])
                 : "r"(a[0]), "r"(a[1]), "r"(a[2]), "r"(a[3]), "r"(b0), "r"(b1));
}

// Exact packed sincos (2 angles): pi-based magic-number reduction, 2-term
// Cody-Waite, Taylor deg-7/deg-8, sign from mantissa LSB. Valid |a| < ~1e6.
__device__ __forceinline__ void sincos2p(u64 a2, u64& s_out, u64& c_out) {
    const float MAGIC = 12582912.0f;            // 1.5 * 2^23
    u64 g2 = fma2(a2, K2(0.31830988618379067f), K2(MAGIC));
    float g0f, g1f; unpack2(g2, g0f, g1f);
    uint32_t m0 = __float_as_uint(g0f) << 31;
    uint32_t m1 = __float_as_uint(g1f) << 31;
    u64 mask = pack2u(m0, m1);
    u64 j2 = sub2(g2, K2(MAGIC));
    u64 r2 = fma2(j2, K2(-3.14159274101257324f), a2);
    r2 = fma2(j2, K2(8.74227765735e-08f), r2);      // -(pi - fp32(pi))
    u64 z = mul2(r2, r2);
    u64 p = fma2(z, K2(-1.98412698e-04f), K2(8.33333333e-03f));
    p = fma2(p, z, K2(-1.66666667e-01f));
    u64 rz = mul2(r2, z);
    u64 s = fma2(p, rz, r2);
    u64 q = fma2(z, K2(2.48015873e-05f), K2(-1.38888889e-03f));
    q = fma2(q, z, K2(4.16666667e-02f));
    q = fma2(q, z, K2(-0.5f));
    u64 c = fma2(q, z, K2(1.0f));
    s_out = s ^ mask;
    c_out = c ^ mask;
}

// Shared rows padded to 80B (20 u32): conflict-free ldmatrix.
#define ROWU 20

__global__ void __launch_bounds__(TPB, 6) nerf_hmma_kernel(
    const float* __restrict__ x,
    const float* __restrict__ W1,
    const float* __restrict__ b1,
    const float* __restrict__ W2,
    const float* __restrict__ b2,
    float* __restrict__ out, int N)
{
    __shared__ __align__(16) uint32_t sWTH[HID * ROWU];      // W1^T [n][k] fp16
    __shared__ __align__(16) uint32_t sFH[4][32 * ROWU];     // features fp16, per warp
    __shared__ float2 sBW[HID];                              // (b1, W2)

    int tid = threadIdx.x;
    int lane = tid & 31;
    int w = tid >> 5;
    int t4 = lane & 3, g4 = lane >> 2;

    // Build W1^T fp16 tile (k >= NIN zero-padded)
    {
        __half* wh = (__half*)sWTH;
        for (int idx = tid; idx < HID * 32; idx += TPB) {
            int n = idx >> 5, k = idx & 31;
            float v = (k < NIN) ? W1[k * HID + n] : 0.0f;
            wh[n * (ROWU * 2) + k] = __float2half_rn(v);
        }
    }
    if (tid < HID) sBW[tid] = make_float2(b1[tid], W2[tid]);
    __syncthreads();

    // Layer-1 B fragments: [nc][ks][reg]
    uint32_t bh[4][2][2];
    {
        int l16 = lane & 15;
        int rN = l16 & 7;
        int inM1 = l16 >> 3;
        uint32_t baseH = smem_u32(sWTH);
        #pragma unroll
        for (int nc = 0; nc < 4; nc++) {
            #pragma unroll
            for (int ks = 0; ks < 2; ks++) {
                uint32_t off = (uint32_t)((nc * 8 + rN) * 80 + (ks * 16 + inM1 * 8) * 2);
                ldmatrix_x2(bh[nc][ks][0], bh[nc][ks][1], baseH + off);
            }
        }
    }
    // b1 per C-fragment column
    float2 bw0[4], bw1[4];
    #pragma unroll
    for (int nc = 0; nc < 4; nc++) {
        bw0[nc] = sBW[nc * 8 + 2 * t4];
        bw1[nc] = sBW[nc * 8 + 2 * t4 + 1];
    }
    // Layer-2 B fragments (W2 broadcast over all 8 n-cols; hi+mid split)
    uint32_t b2h[2][2], b2m[2][2];
    #pragma unroll
    for (int ks = 0; ks < 2; ks++) {
        #pragma unroll
        for (int hp = 0; hp < 2; hp++) {
            int k = ks * 16 + hp * 8 + 2 * t4;
            float w0 = sBW[k].y, w1 = sBW[k + 1].y;
            __half h0 = __float2half_rn(w0), h1 = __float2half_rn(w1);
            float m0f = w0 - __half2float(h0);
            float m1f = w1 - __half2float(h1);
            __half q0 = __float2half_rn(m0f), q1 = __float2half_rn(m1f);
            b2h[ks][hp] = ((uint32_t)__half_as_ushort(h1) << 16) | __half_as_ushort(h0);
            b2m[ks][hp] = ((uint32_t)__half_as_ushort(q1) << 16) | __half_as_ushort(q0);
        }
    }
    float b2v = b2[0];

    uint32_t fhB = smem_u32(&sFH[w][0]);
    const float f1 = exp2f(3.3333333333333335f);
    const float f2 = exp2f(6.666666666666667f);
    const float f3 = 1024.0f;

    int warp_base = blockIdx.x * (ITER * TPB) + w * 32;

    // Prefetch iter-0 coords
    float nx = 0.0f, ny = 0.0f, nz = 0.0f;
    {
        int p = warp_base + lane;
        if (p < N) { nx = x[p * 3]; ny = x[p * 3 + 1]; nz = x[p * 3 + 2]; }
    }

    for (int it = 0; it < ITER; it++) {
        int pbase = warp_base + it * 128;
        float xv = nx, yv = ny, zv = nz;

        // kick off next iter's loads early
        if (it + 1 < ITER) {
            int pn = pbase + 128 + lane;
            nx = ny = nz = 0.0f;
            if (pn < N) { nx = x[pn * 3]; ny = x[pn * 3 + 1]; nz = x[pn * 3 + 2]; }
        }

        // 27 features: [x,y,z, per-band sin(xyz), cos(xyz)]
        float f[28];
        f[0] = xv; f[1] = yv; f[2] = zv; f[27] = 0.0f;
        // Bands 1, f1: MUFU (6 angles, small args — RRO reduction safe)
        {
            f[3] = __sinf(xv); f[4] = __sinf(yv); f[5] = __sinf(zv);
            f[6] = __cosf(xv); f[7] = __cosf(yv); f[8] = __cosf(zv);
            float ax = xv * f1, ay = yv * f1, az = zv * f1;
            f[9]  = __sinf(ax); f[10] = __sinf(ay); f[11] = __sinf(az);
            f[12] = __cosf(ax); f[13] = __cosf(ay); f[14] = __cosf(az);
        }
        // Bands f2, 1024: exact packed-FMA path (3 calls, 6 angles)
        {
            u64 s, c;
            sincos2p(mul2(pack2(xv, yv), K2(f2)), s, c);
            unpack2(s, f[15], f[16]); unpack2(c, f[18], f[19]);
            sincos2p(mul2(pack2(zv, xv), pack2(f2, f3)), s, c);
            unpack2(s, f[17], f[21]); unpack2(c, f[20], f[24]);
            sincos2p(mul2(pack2(yv, zv), K2(f3)), s, c);
            unpack2(s, f[22], f[23]); unpack2(c, f[25], f[26]);
        }

        // fp16 convert
        uint32_t hi[16];
        #pragma unroll
        for (int c2 = 0; c2 < 14; c2++) {
            CVT_F16X2(hi[c2], f[2 * c2], f[2 * c2 + 1]);
        }
        hi[14] = hi[15] = 0;

        // Store this point's feature row (row = lane), 80B stride
        {
            uint32_t* rh = &sFH[w][lane * ROWU];
            *(uint4*)(rh + 0)  = make_uint4(hi[0], hi[1], hi[2], hi[3]);
            *(uint4*)(rh + 4)  = make_uint4(hi[4], hi[5], hi[6], hi[7]);
            *(uint4*)(rh + 8)  = make_uint4(hi[8], hi[9], hi[10], hi[11]);
            *(uint4*)(rh + 12) = make_uint4(hi[12], hi[13], hi[14], hi[15]);
        }
        __syncwarp();

        // Two m16 tiles of 16 points each
        #pragma unroll
        for (int mt = 0; mt < 2; mt++) {
            int rowl = mt * 16 + (lane & 15);
            uint32_t aoff = (uint32_t)(rowl * 80 + ((lane >> 4) & 1) * 16);
            uint32_t ah[8];
            ldmatrix_x4(ah[0], ah[1], ah[2], ah[3], fhB + aoff);
            ldmatrix_x4(ah[4], ah[5], ah[6], ah[7], fhB + aoff + 32);

            // Layer 1: C initialized with b1
            float C[4][4];
            #pragma unroll
            for (int nc = 0; nc < 4; nc++) {
                C[nc][0] = bw0[nc].x; C[nc][1] = bw1[nc].x;
                C[nc][2] = bw0[nc].x; C[nc][3] = bw1[nc].x;
            }
            #pragma unroll
            for (int nc = 0; nc < 4; nc++) {
                #pragma unroll
                for (int ks = 0; ks < 2; ks++) {
                    mma16816(C[nc], ah + ks * 4, bh[nc][ks][0], bh[nc][ks][1]);
                }
            }

            // Layer 2: relu(C) -> fp16 A fragments, MMA vs W2 (hi+mid), b2 in D
            uint32_t hA[2][4];
            #pragma unroll
            for (int ks = 0; ks < 2; ks++) {
                float* Ca = C[2 * ks];
                float* Cb = C[2 * ks + 1];
                CVT_F16X2(hA[ks][0], fmaxf(Ca[0], 0.0f), fmaxf(Ca[1], 0.0f));
                CVT_F16X2(hA[ks][1], fmaxf(Ca[2], 0.0f), fmaxf(Ca[3], 0.0f));
                CVT_F16X2(hA[ks][2], fmaxf(Cb[0], 0.0f), fmaxf(Cb[1], 0.0f));
                CVT_F16X2(hA[ks][3], fmaxf(Cb[2], 0.0f), fmaxf(Cb[3], 0.0f));
            }
            float D[4] = { b2v, b2v, b2v, b2v };
            mma16816(D, hA[0], b2h[0][0], b2h[0][1]);
            mma16816(D, hA[1], b2h[1][0], b2h[1][1]);
            mma16816(D, hA[0], b2m[0][0], b2m[0][1]);
            mma16816(D, hA[1], b2m[1][0], b2m[1][1]);

            if (t4 == 0) {
                int q0 = pbase + mt * 16 + g4;
                int q1 = q0 + 8;
                if (q0 < N) out[q0] = fmaxf(D[0], 0.0f);
                if (q1 < N) out[q1] = fmaxf(D[2], 0.0f);
            }
        }
        __syncwarp();
    }
}

extern "C" void kernel_launch(void* const* d_in, const int* in_sizes, int n_in,
                              void* d_out, int out_size) {
    const float* x  = (const float*)d_in[0];
    const float* W1 = (const float*)d_in[1];
    const float* b1 = (const float*)d_in[2];
    const float* W2 = (const float*)d_in[3];
    const float* b2 = (const float*)d_in[4];
    float* out = (float*)d_out;

    int N = in_sizes[0] / 3;
    int per_block = ITER * TPB;   // 1024 points per block
    int blocks = (N + per_block - 1) / per_block;
    nerf_hmma_kernel<<<blocks, TPB>>>(x, W1, b1, W2, b2, out, N);
}

// round 17
// speedup vs baseline: 1.1314x; 1.1314x over previous
#include <cuda_runtime.h>
#include <cuda_fp16.h>
#include <cstdint>

// Fused NeRF: MUFU sincos everywhere (exact Cody-Waite pre-reduction for the
// 1024 band) + layer1 mma.sync.m16n8k16 fp16 + layer2 via MMA (W2 hi+mid,
// b2 in D-init). Base-sm_100.
// R15: revert to R13's all-MUFU mix (R14's FMA-path re-add regressed);
// b1 folded in as feature #27 (C-init = 0, frees 8 regs); 6 blocks/SM.

typedef unsigned long long u64;

#define TPB 128
#define ITER 8
#define NIN 27
#define HID 32

// d = { f16(a) in low half, f16(b) in high half }
#define CVT_F16X2(result, a, b) \
    asm("cvt.rn.f16x2.f32 %0, %1, %2;" : "=r"(result) : "f"(b), "f"(a))

__device__ __forceinline__ uint32_t smem_u32(const void* p) {
    uint32_t a; asm("{ .reg .u64 t; cvta.to.shared.u64 t, %1; cvt.u32.u64 %0, t; }" : "=r"(a) : "l"(p));
    return a;
}
__device__ __forceinline__ void ldmatrix_x4(uint32_t& r0, uint32_t& r1, uint32_t& r2, uint32_t& r3, uint32_t addr) {
    asm volatile("ldmatrix.sync.aligned.m8n8.x4.shared.b16 {%0,%1,%2,%3}, [%4];"
                 : "=r"(r0), "=r"(r1), "=r"(r2), "=r"(r3) : "r"(addr));
}
__device__ __forceinline__ void ldmatrix_x2(uint32_t& r0, uint32_t& r1, uint32_t addr) {
    asm volatile("ldmatrix.sync.aligned.m8n8.x2.shared.b16 {%0,%1}, [%2];"
                 : "=r"(r0), "=r"(r1) : "r"(addr));
}
__device__ __forceinline__ void mma16816(float* c, const uint32_t* a, uint32_t b0, uint32_t b1) {
    asm volatile("mma.sync.aligned.m16n8k16.row.col.f32.f16.f16.f32 "
                 "{%0,%1,%2,%3},{%4,%5,%6,%7},{%8,%9},{%0,%1,%2,%3};"
                 : "+f"(c[0]), "+f"(c[1]), "+f"(c[2]), "+f"(c[3])
                 : "r"(a[0]), "r"(a[1]), "r"(a[2]), "r"(a[3]), "r"(b0), "r"(b1));
}

// Band-1024 sincos: EXACT magic-number Cody-Waite reduction (theta = j*pi + r),
// then MUFU on the small reduced r (|r| <= pi/2). Sign (-1)^j via LSB mask.
__device__ __forceinline__ void sincos_big(float a, float& s, float& c) {
    const float MAGIC = 12582912.0f;            // 1.5 * 2^23
    float g = fmaf(a, 0.31830988618379067f, MAGIC);
    uint32_t m = __float_as_uint(g) << 31;
    float j = g - MAGIC;
    float r = fmaf(j, -3.14159274101257324f, a);
    r = fmaf(j, 8.74227765735e-08f, r);         // -(pi - fp32(pi))
    s = __uint_as_float(__float_as_uint(__sinf(r)) ^ m);
    c = __uint_as_float(__float_as_uint(__cosf(r)) ^ m);
}

// Shared rows padded to 80B (20 u32): conflict-free ldmatrix.
#define ROWU 20

__global__ void __launch_bounds__(TPB, 6) nerf_hmma_kernel(
    const float* __restrict__ x,
    const float* __restrict__ W1,
    const float* __restrict__ b1,
    const float* __restrict__ W2,
    const float* __restrict__ b2,
    float* __restrict__ out, int N)
{
    __shared__ __align__(16) uint32_t sWTH[HID * ROWU];      // W1^T [n][k] fp16 (+b1 at k=27)
    __shared__ __align__(16) uint32_t sFH[4][32 * ROWU];     // features fp16, per warp
    __shared__ float sW2s[HID];

    int tid = threadIdx.x;
    int lane = tid & 31;
    int w = tid >> 5;
    int t4 = lane & 3, g4 = lane >> 2;

    // Build W1^T fp16 tile; k=27 row carries b1 (feature 27 == 1.0)
    {
        __half* wh = (__half*)sWTH;
        for (int idx = tid; idx < HID * 32; idx += TPB) {
            int n = idx >> 5, k = idx & 31;
            float v = (k < NIN) ? W1[k * HID + n] : (k == NIN ? b1[n] : 0.0f);
            wh[n * (ROWU * 2) + k] = __float2half_rn(v);
        }
    }
    if (tid < HID) sW2s[tid] = W2[tid];
    __syncthreads();

    // Layer-1 B fragments: [nc][ks][reg]
    uint32_t bh[4][2][2];
    {
        int l16 = lane & 15;
        int rN = l16 & 7;
        int inM1 = l16 >> 3;
        uint32_t baseH = smem_u32(sWTH);
        #pragma unroll
        for (int nc = 0; nc < 4; nc++) {
            #pragma unroll
            for (int ks = 0; ks < 2; ks++) {
                uint32_t off = (uint32_t)((nc * 8 + rN) * 80 + (ks * 16 + inM1 * 8) * 2);
                ldmatrix_x2(bh[nc][ks][0], bh[nc][ks][1], baseH + off);
            }
        }
    }
    // Layer-2 B fragments (W2 broadcast over all 8 n-cols; hi+mid split)
    uint32_t b2h[2][2], b2m[2][2];
    #pragma unroll
    for (int ks = 0; ks < 2; ks++) {
        #pragma unroll
        for (int hp = 0; hp < 2; hp++) {
            int k = ks * 16 + hp * 8 + 2 * t4;
            float w0 = sW2s[k], w1 = sW2s[k + 1];
            __half h0 = __float2half_rn(w0), h1 = __float2half_rn(w1);
            float m0f = w0 - __half2float(h0);
            float m1f = w1 - __half2float(h1);
            __half q0 = __float2half_rn(m0f), q1 = __float2half_rn(m1f);
            b2h[ks][hp] = ((uint32_t)__half_as_ushort(h1) << 16) | __half_as_ushort(h0);
            b2m[ks][hp] = ((uint32_t)__half_as_ushort(q1) << 16) | __half_as_ushort(q0);
        }
    }
    float b2v = b2[0];

    uint32_t fhB = smem_u32(&sFH[w][0]);
    const float f1 = exp2f(3.3333333333333335f);
    const float f2 = exp2f(6.666666666666667f);
    const float f3 = 1024.0f;

    int warp_base = blockIdx.x * (ITER * TPB) + w * 32;

    // Prefetch iter-0 coords
    float nx = 0.0f, ny = 0.0f, nz = 0.0f;
    {
        int p = warp_base + lane;
        if (p < N) { nx = x[p * 3]; ny = x[p * 3 + 1]; nz = x[p * 3 + 2]; }
    }

    for (int it = 0; it < ITER; it++) {
        int pbase = warp_base + it * 128;
        float xv = nx, yv = ny, zv = nz;

        // kick off next iter's loads early
        if (it + 1 < ITER) {
            int pn = pbase + 128 + lane;
            nx = ny = nz = 0.0f;
            if (pn < N) { nx = x[pn * 3]; ny = x[pn * 3 + 1]; nz = x[pn * 3 + 2]; }
        }

        // 28 features: [x,y,z, per-band sin(xyz), cos(xyz), 1.0 (bias)]
        float f[28];
        f[0] = xv; f[1] = yv; f[2] = zv; f[27] = 1.0f;
        // Bands 1, f1, f2: direct MUFU (RRO reduction err ~|a|*4e-7, safe)
        {
            f[3] = __sinf(xv); f[4] = __sinf(yv); f[5] = __sinf(zv);
            f[6] = __cosf(xv); f[7] = __cosf(yv); f[8] = __cosf(zv);
            float ax = xv * f1, ay = yv * f1, az = zv * f1;
            f[9]  = __sinf(ax); f[10] = __sinf(ay); f[11] = __sinf(az);
            f[12] = __cosf(ax); f[13] = __cosf(ay); f[14] = __cosf(az);
            float bx = xv * f2, by = yv * f2, bz = zv * f2;
            f[15] = __sinf(bx); f[16] = __sinf(by); f[17] = __sinf(bz);
            f[18] = __cosf(bx); f[19] = __cosf(by); f[20] = __cosf(bz);
        }
        // Band 1024: exact reduction + MUFU on reduced angle
        sincos_big(xv * f3, f[21], f[24]);
        sincos_big(yv * f3, f[22], f[25]);
        sincos_big(zv * f3, f[23], f[26]);

        // fp16 convert
        uint32_t hi[16];
        #pragma unroll
        for (int c2 = 0; c2 < 14; c2++) {
            CVT_F16X2(hi[c2], f[2 * c2], f[2 * c2 + 1]);
        }
        hi[14] = 0;
        hi[13] = (hi[13] & 0x0000FFFFu) | 0x3C000000u;   // f[27] = 1.0h in high half
        hi[15] = 0;

        // Store this point's feature row (row = lane), 80B stride
        {
            uint32_t* rh = &sFH[w][lane * ROWU];
            *(uint4*)(rh + 0)  = make_uint4(hi[0], hi[1], hi[2], hi[3]);
            *(uint4*)(rh + 4)  = make_uint4(hi[4], hi[5], hi[6], hi[7]);
            *(uint4*)(rh + 8)  = make_uint4(hi[8], hi[9], hi[10], hi[11]);
            *(uint4*)(rh + 12) = make_uint4(hi[12], hi[13], hi[14], hi[15]);
        }
        __syncwarp();

        // Two m16 tiles of 16 points each
        #pragma unroll
        for (int mt = 0; mt < 2; mt++) {
            int rowl = mt * 16 + (lane & 15);
            uint32_t aoff = (uint32_t)(rowl * 80 + ((lane >> 4) & 1) * 16);
            uint32_t ah[8];
            ldmatrix_x4(ah[0], ah[1], ah[2], ah[3], fhB + aoff);
            ldmatrix_x4(ah[4], ah[5], ah[6], ah[7], fhB + aoff + 32);

            // Layer 1: C = 0 (bias lives in W1^T row 27)
            float C[4][4];
            #pragma unroll
            for (int nc = 0; nc < 4; nc++)
                { C[nc][0] = C[nc][1] = C[nc][2] = C[nc][3] = 0.0f; }
            #pragma unroll
            for (int nc = 0; nc < 4; nc++) {
                #pragma unroll
                for (int ks = 0; ks < 2; ks++) {
                    mma16816(C[nc], ah + ks * 4, bh[nc][ks][0], bh[nc][ks][1]);
                }
            }

            // Layer 2: relu(C) -> fp16 A fragments, MMA vs W2 (hi+mid), b2 in D
            uint32_t hA[2][4];
            #pragma unroll
            for (int ks = 0; ks < 2; ks++) {
                float* Ca = C[2 * ks];
                float* Cb = C[2 * ks + 1];
                CVT_F16X2(hA[ks][0], fmaxf(Ca[0], 0.0f), fmaxf(Ca[1], 0.0f));
                CVT_F16X2(hA[ks][1], fmaxf(Ca[2], 0.0f), fmaxf(Ca[3], 0.0f));
                CVT_F16X2(hA[ks][2], fmaxf(Cb[0], 0.0f), fmaxf(Cb[1], 0.0f));
                CVT_F16X2(hA[ks][3], fmaxf(Cb[2], 0.0f), fmaxf(Cb[3], 0.0f));
            }
            float D[4] = { b2v, b2v, b2v, b2v };
            mma16816(D, hA[0], b2h[0][0], b2h[0][1]);
            mma16816(D, hA[1], b2h[1][0], b2h[1][1]);
            mma16816(D, hA[0], b2m[0][0], b2m[0][1]);
            mma16816(D, hA[1], b2m[1][0], b2m[1][1]);

            if (t4 == 0) {
                int q0 = pbase + mt * 16 + g4;
                int q1 = q0 + 8;
                if (q0 < N) out[q0] = fmaxf(D[0], 0.0f);
                if (q1 < N) out[q1] = fmaxf(D[2], 0.0f);
            }
        }
        __syncwarp();
    }
}

extern "C" void kernel_launch(void* const* d_in, const int* in_sizes, int n_in,
                              void* d_out, int out_size) {
    const float* x  = (const float*)d_in[0];
    const float* W1 = (const float*)d_in[1];
    const float* b1 = (const float*)d_in[2];
    const float* W2 = (const float*)d_in[3];
    const float* b2 = (const float*)d_in[4];
    float* out = (float*)d_out;

    int N = in_sizes[0] / 3;
    int per_block = ITER * TPB;   // 1024 points per block
    int blocks = (N + per_block - 1) / per_block;
    nerf_hmma_kernel<<<blocks, TPB>>>(x, W1, b1, W2, b2, out, N);
}